// round 4
// baseline (speedup 1.0000x reference)
#include <cuda_runtime.h>
#include <cuda_bf16.h>

// Problem constants
#define MAXN 100000
#define NGRAPH 512
#define DMAX 64

// -------- device scratch (no allocations allowed) --------
__device__ float g_degf[MAXN];
__device__ float g_dis[MAXN];
__device__ float g_hp  [MAXN * DMAX];   // h' = (x@W)*dis  (read-only during scatter)
__device__ float g_agg [MAXN * DMAX];   // init = h', scatter target
__device__ float g_out [MAXN * DMAX];   // layer output (input of next layer)
__device__ float g_pool[NGRAPH * DMAX];
__device__ float g_cnt [NGRAPH];

// -------- zero init of per-call accumulators --------
__global__ void zero_kernel(int n) {
    int i = blockIdx.x * blockDim.x + threadIdx.x;
    if (i < n)            g_degf[i] = 0.f;
    if (i < NGRAPH*DMAX)  g_pool[i] = 0.f;
    if (i < NGRAPH)       g_cnt[i]  = 0.f;
}

// -------- degree + rsqrt --------
__global__ void deg_kernel(const int* __restrict__ dst, int E) {
    int i = blockIdx.x * blockDim.x + threadIdx.x;
    if (i < E) atomicAdd(&g_degf[__ldg(&dst[i])], 1.0f);
}

__global__ void dis_kernel(int n) {
    int i = blockIdx.x * blockDim.x + threadIdx.x;
    if (i < n) g_dis[i] = rsqrtf(g_degf[i] + 1.0f);
}

// -------- GEMM + pre-scale by dis; writes h' into g_hp AND g_agg (self loop init) --------
template<int K, int M, int R>
__global__ void gemm_scale_kernel(const float* __restrict__ Xext, int xsel,
                                  const float* __restrict__ W, int N) {
    __shared__ float sw[K * M];
    __shared__ float sx[R * K];
    const float* __restrict__ X = (xsel == 0) ? Xext : g_out;

    for (int i = threadIdx.x; i < K * M; i += blockDim.x) sw[i] = W[i];
    int row0 = blockIdx.x * R;
    int nrows = N - row0; if (nrows > R) nrows = R;
    if (nrows <= 0) return;
    for (int i = threadIdx.x; i < nrows * K; i += blockDim.x)
        sx[i] = X[(long long)row0 * K + i];
    __syncthreads();

    for (int idx = threadIdx.x; idx < nrows * M; idx += blockDim.x) {
        int r = idx / M, c = idx - r * M;
        const float* xr = &sx[r * K];
        float acc = 0.f;
        #pragma unroll 16
        for (int k = 0; k < K; k++) acc += xr[k] * sw[k * M + c];
        float v = acc * g_dis[row0 + r];
        long long o = (long long)(row0 + r) * M + c;
        g_hp[o]  = v;
        g_agg[o] = v;   // self-loop contribution preinstalled
    }
}

// -------- per-edge scatter: agg[dst] += hp[src]  (warp per edge, lane per feature) --------
template<int D>
__global__ void __launch_bounds__(256)
edge_scatter_kernel(const int* __restrict__ src,
                    const int* __restrict__ dst, int E) {
    int warp = (blockIdx.x * blockDim.x + threadIdx.x) >> 5;
    int lane = threadIdx.x & 31;
    if (warp >= E) return;
    int s = __ldg(&src[warp]);
    int d = __ldg(&dst[warp]);
    const float* __restrict__ hs = &g_hp[(long long)s * D];
    float* __restrict__ ad = &g_agg[(long long)d * D];
    #pragma unroll
    for (int f = lane; f < D; f += 32)
        atomicAdd(&ad[f], hs[f]);
}

// -------- finalize: out = relu(dis * agg + b) --------
template<int M>
__global__ void finalize_kernel(const float* __restrict__ b, int N) {
    long long idx = (long long)blockIdx.x * blockDim.x + threadIdx.x;
    if (idx >= (long long)N * M) return;
    int i = (int)(idx / M);
    int c = (int)(idx - (long long)i * M);
    float v = g_dis[i] * g_agg[idx] + b[c];
    g_out[idx] = fmaxf(v, 0.f);
}

// -------- mean pool (batch is sorted -> run-length accumulate, flush on change) --------
__global__ void pool_kernel(const int* __restrict__ batch, int N) {
    const int CH = 64;
    int n0 = blockIdx.x * CH;
    int c  = threadIdx.x;           // 64 threads, one per feature
    int nend = n0 + CH; if (nend > N) nend = N;
    float acc = 0.f, cacc = 0.f;
    int curg = -1;
    for (int n = n0; n < nend; n++) {
        int g = batch[n];
        if (g != curg) {
            if (curg >= 0) {
                atomicAdd(&g_pool[curg * DMAX + c], acc);
                if (c == 0) atomicAdd(&g_cnt[curg], cacc);
            }
            curg = g; acc = 0.f; cacc = 0.f;
        }
        acc  += g_out[(long long)n * DMAX + c];
        cacc += 1.0f;
    }
    if (curg >= 0) {
        atomicAdd(&g_pool[curg * DMAX + c], acc);
        if (c == 0) atomicAdd(&g_cnt[curg], cacc);
    }
}

// -------- MLP + softmax: one thread per graph --------
__global__ void mlp_kernel(const float* __restrict__ fc1w, const float* __restrict__ fc1b,
                           const float* __restrict__ fc2w, const float* __restrict__ fc2b,
                           float* __restrict__ out) {
    int g = blockIdx.x * blockDim.x + threadIdx.x;
    if (g >= NGRAPH) return;
    float invc = 1.0f / fmaxf(g_cnt[g], 1.0f);
    float p[64];
    #pragma unroll
    for (int i = 0; i < 64; i++) p[i] = g_pool[g * DMAX + i] * invc;
    float z[32];
    #pragma unroll 4
    for (int j = 0; j < 32; j++) {
        float a = fc1b[j];
        #pragma unroll
        for (int i = 0; i < 64; i++) a += p[i] * fc1w[i * 32 + j];
        z[j] = fmaxf(a, 0.f);
    }
    float l[16]; float mx = -1e30f;
    #pragma unroll
    for (int k = 0; k < 16; k++) {
        float a = fc2b[k];
        #pragma unroll
        for (int j = 0; j < 32; j++) a += z[j] * fc2w[j * 16 + k];
        l[k] = a; mx = fmaxf(mx, a);
    }
    float s = 0.f;
    #pragma unroll
    for (int k = 0; k < 16; k++) { l[k] = expf(l[k] - mx); s += l[k]; }
    float invs = 1.0f / s;
    #pragma unroll
    for (int k = 0; k < 16; k++) out[g * 16 + k] = l[k] * invs;
}

extern "C" void kernel_launch(void* const* d_in, const int* in_sizes, int n_in,
                              void* d_out, int out_size) {
    const float* x     = (const float*)d_in[0];
    const int*   eidx  = (const int*)d_in[1];   // int32 (JAX x64 disabled)
    const int*   batch = (const int*)d_in[2];
    const float* W1 = (const float*)d_in[3];
    const float* b1 = (const float*)d_in[4];
    const float* W2 = (const float*)d_in[5];
    const float* b2 = (const float*)d_in[6];
    const float* W3 = (const float*)d_in[7];
    const float* b3 = (const float*)d_in[8];
    const float* fc1w = (const float*)d_in[9];
    const float* fc1b = (const float*)d_in[10];
    const float* fc2w = (const float*)d_in[11];
    const float* fc2b = (const float*)d_in[12];
    float* out = (float*)d_out;

    int N = in_sizes[0] / 128;
    int E = in_sizes[1] / 2;
    const int* src = eidx;
    const int* dst = eidx + E;

    // 1) zero accumulators
    {
        int n = N; if (n < NGRAPH * DMAX) n = NGRAPH * DMAX;
        zero_kernel<<<(n + 255) / 256, 256>>>(N);
    }
    // 2) degree + dis
    deg_kernel<<<(E + 255) / 256, 256>>>(dst, E);
    dis_kernel<<<(N + 255) / 256, 256>>>(N);

    int ewarps_blocks = (E + 7) / 8;   // 8 warps per 256-thread block, warp per edge
    int gemm_blocks = (N + 15) / 16;

    // ---- Layer 1: 128 -> 32 ----
    gemm_scale_kernel<128, 32, 16><<<gemm_blocks, 256>>>(x, 0, W1, N);
    edge_scatter_kernel<32><<<ewarps_blocks, 256>>>(src, dst, E);
    finalize_kernel<32><<<((long long)N * 32 + 255) / 256, 256>>>(b1, N);

    // ---- Layer 2: 32 -> 48 ----
    gemm_scale_kernel<32, 48, 16><<<gemm_blocks, 256>>>(nullptr, 1, W2, N);
    edge_scatter_kernel<48><<<ewarps_blocks, 256>>>(src, dst, E);
    finalize_kernel<48><<<((long long)N * 48 + 255) / 256, 256>>>(b2, N);

    // ---- Layer 3: 48 -> 64 ----
    gemm_scale_kernel<48, 64, 16><<<gemm_blocks, 256>>>(nullptr, 1, W3, N);
    edge_scatter_kernel<64><<<ewarps_blocks, 256>>>(src, dst, E);
    finalize_kernel<64><<<((long long)N * 64 + 255) / 256, 256>>>(b3, N);

    // ---- pool + MLP + softmax ----
    pool_kernel<<<(N + 63) / 64, 64>>>(batch, N);
    mlp_kernel<<<(NGRAPH + 255) / 256, 256>>>(fc1w, fc1b, fc2w, fc2b, out);
}

// round 5
// speedup vs baseline: 2.7134x; 2.7134x over previous
#include <cuda_runtime.h>
#include <cuda_bf16.h>

#define MAXN 100000
#define MAXE 3200000
#define NGRAPH 512
#define DMAX 64

// -------- device scratch --------
__device__ int   g_degcnt[MAXN];       // in-degree (int)
__device__ int   g_rs    [MAXN];       // CSR row start (exclusive scan of deg)
__device__ int   g_cursor[MAXN];       // fill cursor
__device__ int   g_bsum  [512];
__device__ int   g_boff  [512];
__device__ int   g_csrc  [MAXE];       // CSR: src ids grouped by dst
__device__ float g_dis   [MAXN];
__device__ float g_hp    [MAXN * DMAX]; // h' = (x@W)*dis
__device__ float g_out   [MAXN * DMAX]; // layer output
__device__ float g_pool  [NGRAPH * DMAX];
__device__ float g_cnt   [NGRAPH];

// -------- zero init --------
__global__ void zero_kernel(int n) {
    int i = blockIdx.x * blockDim.x + threadIdx.x;
    if (i < n)           g_degcnt[i] = 0;
    if (i < NGRAPH*DMAX) g_pool[i] = 0.f;
    if (i < NGRAPH)      g_cnt[i]  = 0.f;
}

// -------- degree --------
__global__ void deg_kernel(const int* __restrict__ dst, int E) {
    int i = blockIdx.x * blockDim.x + threadIdx.x;
    if (i < E) atomicAdd(&g_degcnt[__ldg(&dst[i])], 1);
}

// -------- exclusive scan of degcnt (3 kernels) --------
__global__ void scan1_kernel(int N) {
    __shared__ int s[512];
    int t = threadIdx.x;
    int i = blockIdx.x * 512 + t;
    int v = (i < N) ? g_degcnt[i] : 0;
    s[t] = v; __syncthreads();
    for (int o = 1; o < 512; o <<= 1) {
        int u = (t >= o) ? s[t - o] : 0;
        __syncthreads(); s[t] += u; __syncthreads();
    }
    if (i < N) g_rs[i] = s[t] - v;           // within-block exclusive
    if (t == 511) g_bsum[blockIdx.x] = s[511];
}
__global__ void scan2_kernel(int nb) {
    __shared__ int s[512];
    int t = threadIdx.x;
    int v = (t < nb) ? g_bsum[t] : 0;
    s[t] = v; __syncthreads();
    for (int o = 1; o < 512; o <<= 1) {
        int u = (t >= o) ? s[t - o] : 0;
        __syncthreads(); s[t] += u; __syncthreads();
    }
    if (t < nb) g_boff[t] = s[t] - v;        // exclusive block offsets
}
__global__ void scan3_kernel(int N) {
    int i = blockIdx.x * blockDim.x + threadIdx.x;
    if (i < N) {
        int r = g_rs[i] + g_boff[i >> 9];
        g_rs[i] = r;
        g_cursor[i] = r;
        g_dis[i] = rsqrtf((float)g_degcnt[i] + 1.0f);
    }
}

// -------- CSR fill: group src by dst --------
__global__ void fill_csr_kernel(const int* __restrict__ src,
                                const int* __restrict__ dst, int E) {
    int i = blockIdx.x * blockDim.x + threadIdx.x;
    if (i < E) {
        int d = __ldg(&dst[i]);
        int p = atomicAdd(&g_cursor[d], 1);
        g_csrc[p] = __ldg(&src[i]);
    }
}

// -------- GEMM + pre-scale by dis: hp = (X@W) * dis --------
// thread = (row, 4 columns); W float4 from smem, x broadcast from padded smem
template<int K, int M, int R>
__global__ void gemm_kernel(const float* __restrict__ Xext, int xsel,
                            const float* __restrict__ W, int N) {
    constexpr int G = M / 4;
    __shared__ float4 sw[K * G];
    __shared__ float  sx[R * (K + 1)];
    const float* __restrict__ X = xsel ? g_out : Xext;
    int tid = threadIdx.x;
    const float4* W4 = (const float4*)W;
    for (int i = tid; i < K * G; i += blockDim.x) sw[i] = W4[i];
    int row0 = blockIdx.x * R;
    int nrows = N - row0; if (nrows > R) nrows = R;
    if (nrows <= 0) return;
    for (int i = tid; i < nrows * K; i += blockDim.x) {
        int r = i / K, k = i - r * K;
        sx[r * (K + 1) + k] = X[(size_t)(row0 + r) * K + k];
    }
    __syncthreads();
    int r = tid / G, g = tid - r * G;
    if (r < nrows) {
        float4 acc = {0.f, 0.f, 0.f, 0.f};
        const float* xr = &sx[r * (K + 1)];
        #pragma unroll 8
        for (int k = 0; k < K; k++) {
            float xv = xr[k];
            float4 wv = sw[k * G + g];
            acc.x += xv * wv.x; acc.y += xv * wv.y;
            acc.z += xv * wv.z; acc.w += xv * wv.w;
        }
        float ds = g_dis[row0 + r];
        acc.x *= ds; acc.y *= ds; acc.z *= ds; acc.w *= ds;
        ((float4*)g_hp)[(size_t)(row0 + r) * G + g] = acc;
    }
}

// -------- gather + finalize: out = relu(dis * (sum_{src} hp[src] + hp[self]) + b) --------
template<int D>
__global__ void __launch_bounds__(256)
gather_kernel(const float* __restrict__ bias, int N) {
    int v = (int)((blockIdx.x * blockDim.x + threadIdx.x) >> 5);
    int lane = threadIdx.x & 31;
    if (v >= N) return;
    int rs = g_rs[v];
    int dg = g_degcnt[v];
    float a0 = 0.f, a1 = 0.f;
    const float* __restrict__ hp = g_hp;

    for (int j0 = 0; j0 < dg; j0 += 32) {
        int jj = j0 + lane;
        int sv = (jj < dg) ? __ldg(&g_csrc[rs + jj]) : 0;
        int cnt = dg - j0; if (cnt > 32) cnt = 32;
        if (cnt == 32) {
            #pragma unroll 8
            for (int k = 0; k < 32; k++) {
                int s = __shfl_sync(0xffffffffu, sv, k);
                if (D == 64) {
                    float2 h = *(const float2*)(hp + (size_t)s * 64 + lane * 2);
                    a0 += h.x; a1 += h.y;
                } else if (D == 48) {
                    a0 += hp[(size_t)s * 48 + lane];
                    if (lane < 16) a1 += hp[(size_t)s * 48 + 32 + lane];
                } else {
                    a0 += hp[(size_t)s * 32 + lane];
                }
            }
        } else {
            for (int k = 0; k < cnt; k++) {
                int s = __shfl_sync(0xffffffffu, sv, k);
                if (D == 64) {
                    float2 h = *(const float2*)(hp + (size_t)s * 64 + lane * 2);
                    a0 += h.x; a1 += h.y;
                } else if (D == 48) {
                    a0 += hp[(size_t)s * 48 + lane];
                    if (lane < 16) a1 += hp[(size_t)s * 48 + 32 + lane];
                } else {
                    a0 += hp[(size_t)s * 32 + lane];
                }
            }
        }
    }
    // self loop
    if (D == 64) {
        float2 h = *(const float2*)(hp + (size_t)v * 64 + lane * 2);
        a0 += h.x; a1 += h.y;
    } else if (D == 48) {
        a0 += hp[(size_t)v * 48 + lane];
        if (lane < 16) a1 += hp[(size_t)v * 48 + 32 + lane];
    } else {
        a0 += hp[(size_t)v * 32 + lane];
    }
    float ds = g_dis[v];
    if (D == 64) {
        float2 o;
        o.x = fmaxf(ds * a0 + __ldg(&bias[lane * 2]), 0.f);
        o.y = fmaxf(ds * a1 + __ldg(&bias[lane * 2 + 1]), 0.f);
        *(float2*)(g_out + (size_t)v * 64 + lane * 2) = o;
    } else if (D == 48) {
        g_out[(size_t)v * 48 + lane] = fmaxf(ds * a0 + __ldg(&bias[lane]), 0.f);
        if (lane < 16)
            g_out[(size_t)v * 48 + 32 + lane] = fmaxf(ds * a1 + __ldg(&bias[32 + lane]), 0.f);
    } else {
        g_out[(size_t)v * 32 + lane] = fmaxf(ds * a0 + __ldg(&bias[lane]), 0.f);
    }
}

// -------- mean pool (batch sorted -> run-length accumulate) --------
__global__ void pool_kernel(const int* __restrict__ batch, int N) {
    const int CH = 64;
    int n0 = blockIdx.x * CH;
    int c  = threadIdx.x;
    int nend = n0 + CH; if (nend > N) nend = N;
    float acc = 0.f, cacc = 0.f;
    int curg = -1;
    for (int n = n0; n < nend; n++) {
        int g = batch[n];
        if (g != curg) {
            if (curg >= 0) {
                atomicAdd(&g_pool[curg * DMAX + c], acc);
                if (c == 0) atomicAdd(&g_cnt[curg], cacc);
            }
            curg = g; acc = 0.f; cacc = 0.f;
        }
        acc  += g_out[(size_t)n * DMAX + c];
        cacc += 1.0f;
    }
    if (curg >= 0) {
        atomicAdd(&g_pool[curg * DMAX + c], acc);
        if (c == 0) atomicAdd(&g_cnt[curg], cacc);
    }
}

// -------- MLP + softmax --------
__global__ void mlp_kernel(const float* __restrict__ fc1w, const float* __restrict__ fc1b,
                           const float* __restrict__ fc2w, const float* __restrict__ fc2b,
                           float* __restrict__ out) {
    int g = blockIdx.x * blockDim.x + threadIdx.x;
    if (g >= NGRAPH) return;
    float invc = 1.0f / fmaxf(g_cnt[g], 1.0f);
    float p[64];
    #pragma unroll
    for (int i = 0; i < 64; i++) p[i] = g_pool[g * DMAX + i] * invc;
    float z[32];
    #pragma unroll 4
    for (int j = 0; j < 32; j++) {
        float a = fc1b[j];
        #pragma unroll
        for (int i = 0; i < 64; i++) a += p[i] * fc1w[i * 32 + j];
        z[j] = fmaxf(a, 0.f);
    }
    float l[16]; float mx = -1e30f;
    #pragma unroll
    for (int k = 0; k < 16; k++) {
        float a = fc2b[k];
        #pragma unroll
        for (int j = 0; j < 32; j++) a += z[j] * fc2w[j * 16 + k];
        l[k] = a; mx = fmaxf(mx, a);
    }
    float s = 0.f;
    #pragma unroll
    for (int k = 0; k < 16; k++) { l[k] = expf(l[k] - mx); s += l[k]; }
    float invs = 1.0f / s;
    #pragma unroll
    for (int k = 0; k < 16; k++) out[g * 16 + k] = l[k] * invs;
}

extern "C" void kernel_launch(void* const* d_in, const int* in_sizes, int n_in,
                              void* d_out, int out_size) {
    const float* x     = (const float*)d_in[0];
    const int*   eidx  = (const int*)d_in[1];   // int32
    const int*   batch = (const int*)d_in[2];
    const float* W1 = (const float*)d_in[3];
    const float* b1 = (const float*)d_in[4];
    const float* W2 = (const float*)d_in[5];
    const float* b2 = (const float*)d_in[6];
    const float* W3 = (const float*)d_in[7];
    const float* b3 = (const float*)d_in[8];
    const float* fc1w = (const float*)d_in[9];
    const float* fc1b = (const float*)d_in[10];
    const float* fc2w = (const float*)d_in[11];
    const float* fc2b = (const float*)d_in[12];
    float* out = (float*)d_out;

    int N = in_sizes[0] / 128;
    int E = in_sizes[1] / 2;
    const int* src = eidx;
    const int* dst = eidx + E;

    // CSR build pipeline
    {
        int n = N; if (n < NGRAPH * DMAX) n = NGRAPH * DMAX;
        zero_kernel<<<(n + 255) / 256, 256>>>(N);
    }
    deg_kernel<<<(E + 255) / 256, 256>>>(dst, E);
    int nb = (N + 511) / 512;
    scan1_kernel<<<nb, 512>>>(N);
    scan2_kernel<<<1, 512>>>(nb);
    scan3_kernel<<<(N + 255) / 256, 256>>>(N);
    fill_csr_kernel<<<(E + 255) / 256, 256>>>(src, dst, E);

    int gth_blocks = (N + 7) / 8;    // warp per node, 8 warps/block
    int gemm_blocks = (N + 15) / 16; // R=16

    // ---- Layer 1: 128 -> 32 ----
    gemm_kernel<128, 32, 16><<<gemm_blocks, 128>>>(x, 0, W1, N);
    gather_kernel<32><<<gth_blocks, 256>>>(b1, N);
    // ---- Layer 2: 32 -> 48 ----
    gemm_kernel<32, 48, 16><<<gemm_blocks, 192>>>(nullptr, 1, W2, N);
    gather_kernel<48><<<gth_blocks, 256>>>(b2, N);
    // ---- Layer 3: 48 -> 64 ----
    gemm_kernel<48, 64, 16><<<gemm_blocks, 256>>>(nullptr, 1, W3, N);
    gather_kernel<64><<<gth_blocks, 256>>>(b3, N);

    // ---- pool + MLP + softmax ----
    pool_kernel<<<(N + 63) / 64, 64>>>(batch, N);
    mlp_kernel<<<(NGRAPH + 255) / 256, 256>>>(fc1w, fc1b, fc2w, fc2b, out);
}

// round 6
// speedup vs baseline: 2.7506x; 1.0137x over previous
#include <cuda_runtime.h>
#include <cuda_bf16.h>

#define MAXN 100000
#define MAXE 3200000
#define NGRAPH 512
#define DMAX 64

// -------- device scratch --------
__device__ int   g_degcnt[MAXN];
__device__ int   g_rs    [MAXN];
__device__ int   g_cursor[MAXN];
__device__ int   g_bsum  [512];
__device__ int   g_boff  [512];
__device__ int   g_csrc  [MAXE];
__device__ float g_dis   [MAXN];
__device__ float g_hp    [MAXN * DMAX];
__device__ float g_out   [MAXN * DMAX];
__device__ float g_pool  [NGRAPH * DMAX];
__device__ float g_cnt   [NGRAPH];

// -------- degree --------
__global__ void deg_kernel(const int* __restrict__ dst, int E) {
    int i = blockIdx.x * blockDim.x + threadIdx.x;
    if (i < E) atomicAdd(&g_degcnt[__ldg(&dst[i])], 1);
}

// -------- dis = rsqrt(deg+1) (only needs deg; runs on fork stream) --------
__global__ void dis_kernel(int N) {
    int i = blockIdx.x * blockDim.x + threadIdx.x;
    if (i < N) g_dis[i] = rsqrtf((float)g_degcnt[i] + 1.0f);
}

// -------- exclusive scan of degcnt --------
__global__ void scan1_kernel(int N) {
    __shared__ int s[512];
    int t = threadIdx.x;
    int i = blockIdx.x * 512 + t;
    int v = (i < N) ? g_degcnt[i] : 0;
    s[t] = v; __syncthreads();
    for (int o = 1; o < 512; o <<= 1) {
        int u = (t >= o) ? s[t - o] : 0;
        __syncthreads(); s[t] += u; __syncthreads();
    }
    if (i < N) g_rs[i] = s[t] - v;
    if (t == 511) g_bsum[blockIdx.x] = s[511];
}
__global__ void scan2_kernel(int nb) {
    __shared__ int s[512];
    int t = threadIdx.x;
    int v = (t < nb) ? g_bsum[t] : 0;
    s[t] = v; __syncthreads();
    for (int o = 1; o < 512; o <<= 1) {
        int u = (t >= o) ? s[t - o] : 0;
        __syncthreads(); s[t] += u; __syncthreads();
    }
    if (t < nb) g_boff[t] = s[t] - v;
}
__global__ void scan3_kernel(int N) {
    int i = blockIdx.x * blockDim.x + threadIdx.x;
    if (i < N) {
        int r = g_rs[i] + g_boff[i >> 9];
        g_rs[i] = r;
        g_cursor[i] = r;
    }
}

// -------- CSR fill --------
__global__ void fill_csr_kernel(const int* __restrict__ src,
                                const int* __restrict__ dst, int E) {
    int i = blockIdx.x * blockDim.x + threadIdx.x;
    if (i < E) {
        int d = __ldg(&dst[i]);
        int p = atomicAdd(&g_cursor[d], 1);
        g_csrc[p] = __ldg(&src[i]);
    }
}

// -------- GEMM + pre-scale by dis: hp = (X@W) * dis --------
template<int K, int M, int R>
__global__ void gemm_kernel(const float* __restrict__ Xext, int xsel,
                            const float* __restrict__ W, int N) {
    constexpr int G = M / 4;
    __shared__ float4 sw[K * G];
    __shared__ float  sx[R * (K + 1)];
    const float* __restrict__ X = xsel ? g_out : Xext;
    int tid = threadIdx.x;
    const float4* W4 = (const float4*)W;
    for (int i = tid; i < K * G; i += blockDim.x) sw[i] = W4[i];
    int row0 = blockIdx.x * R;
    int nrows = N - row0; if (nrows > R) nrows = R;
    if (nrows <= 0) return;
    for (int i = tid; i < nrows * K; i += blockDim.x) {
        int r = i / K, k = i - r * K;
        sx[r * (K + 1) + k] = X[(size_t)(row0 + r) * K + k];
    }
    __syncthreads();
    int r = tid / G, g = tid - r * G;
    if (r < nrows) {
        float4 acc = {0.f, 0.f, 0.f, 0.f};
        const float* xr = &sx[r * (K + 1)];
        #pragma unroll 8
        for (int k = 0; k < K; k++) {
            float xv = xr[k];
            float4 wv = sw[k * G + g];
            acc.x += xv * wv.x; acc.y += xv * wv.y;
            acc.z += xv * wv.z; acc.w += xv * wv.w;
        }
        float ds = g_dis[row0 + r];
        acc.x *= ds; acc.y *= ds; acc.z *= ds; acc.w *= ds;
        ((float4*)g_hp)[(size_t)(row0 + r) * G + g] = acc;
    }
}

// -------- gather + finalize: out = relu(dis * (sum hp[src] + hp[self]) + b) --------
template<int D>
__global__ void __launch_bounds__(256)
gather_kernel(const float* __restrict__ bias, int N) {
    int v = (int)((blockIdx.x * blockDim.x + threadIdx.x) >> 5);
    int lane = threadIdx.x & 31;
    if (v >= N) return;
    int rs = g_rs[v];
    int dg = g_degcnt[v];
    float a0 = 0.f, a1 = 0.f;
    const float* __restrict__ hp = g_hp;

    for (int j0 = 0; j0 < dg; j0 += 32) {
        int jj = j0 + lane;
        int sv = (jj < dg) ? __ldg(&g_csrc[rs + jj]) : 0;
        int cnt = dg - j0; if (cnt > 32) cnt = 32;
        if (cnt == 32) {
            #pragma unroll 8
            for (int k = 0; k < 32; k++) {
                int s = __shfl_sync(0xffffffffu, sv, k);
                if (D == 64) {
                    float2 h = *(const float2*)(hp + (size_t)s * 64 + lane * 2);
                    a0 += h.x; a1 += h.y;
                } else if (D == 48) {
                    a0 += hp[(size_t)s * 48 + lane];
                    if (lane < 16) a1 += hp[(size_t)s * 48 + 32 + lane];
                } else {
                    a0 += hp[(size_t)s * 32 + lane];
                }
            }
        } else {
            for (int k = 0; k < cnt; k++) {
                int s = __shfl_sync(0xffffffffu, sv, k);
                if (D == 64) {
                    float2 h = *(const float2*)(hp + (size_t)s * 64 + lane * 2);
                    a0 += h.x; a1 += h.y;
                } else if (D == 48) {
                    a0 += hp[(size_t)s * 48 + lane];
                    if (lane < 16) a1 += hp[(size_t)s * 48 + 32 + lane];
                } else {
                    a0 += hp[(size_t)s * 32 + lane];
                }
            }
        }
    }
    // self loop
    if (D == 64) {
        float2 h = *(const float2*)(hp + (size_t)v * 64 + lane * 2);
        a0 += h.x; a1 += h.y;
    } else if (D == 48) {
        a0 += hp[(size_t)v * 48 + lane];
        if (lane < 16) a1 += hp[(size_t)v * 48 + 32 + lane];
    } else {
        a0 += hp[(size_t)v * 32 + lane];
    }
    float ds = g_dis[v];
    if (D == 64) {
        float2 o;
        o.x = fmaxf(ds * a0 + __ldg(&bias[lane * 2]), 0.f);
        o.y = fmaxf(ds * a1 + __ldg(&bias[lane * 2 + 1]), 0.f);
        *(float2*)(g_out + (size_t)v * 64 + lane * 2) = o;
    } else if (D == 48) {
        g_out[(size_t)v * 48 + lane] = fmaxf(ds * a0 + __ldg(&bias[lane]), 0.f);
        if (lane < 16)
            g_out[(size_t)v * 48 + 32 + lane] = fmaxf(ds * a1 + __ldg(&bias[32 + lane]), 0.f);
    } else {
        g_out[(size_t)v * 32 + lane] = fmaxf(ds * a0 + __ldg(&bias[lane]), 0.f);
    }
}

// -------- mean pool (batch sorted -> run-length accumulate) --------
__global__ void pool_kernel(const int* __restrict__ batch, int N) {
    const int CH = 64;
    int n0 = blockIdx.x * CH;
    int c  = threadIdx.x;
    int nend = n0 + CH; if (nend > N) nend = N;
    float acc = 0.f, cacc = 0.f;
    int curg = -1;
    for (int n = n0; n < nend; n++) {
        int g = batch[n];
        if (g != curg) {
            if (curg >= 0) {
                atomicAdd(&g_pool[curg * DMAX + c], acc);
                if (c == 0) atomicAdd(&g_cnt[curg], cacc);
            }
            curg = g; acc = 0.f; cacc = 0.f;
        }
        acc  += g_out[(size_t)n * DMAX + c];
        cacc += 1.0f;
    }
    if (curg >= 0) {
        atomicAdd(&g_pool[curg * DMAX + c], acc);
        if (c == 0) atomicAdd(&g_cnt[curg], cacc);
    }
}

// -------- MLP + softmax --------
__global__ void mlp_kernel(const float* __restrict__ fc1w, const float* __restrict__ fc1b,
                           const float* __restrict__ fc2w, const float* __restrict__ fc2b,
                           float* __restrict__ out) {
    int g = blockIdx.x * blockDim.x + threadIdx.x;
    if (g >= NGRAPH) return;
    float invc = 1.0f / fmaxf(g_cnt[g], 1.0f);
    float p[64];
    #pragma unroll
    for (int i = 0; i < 64; i++) p[i] = g_pool[g * DMAX + i] * invc;
    float z[32];
    #pragma unroll 4
    for (int j = 0; j < 32; j++) {
        float a = fc1b[j];
        #pragma unroll
        for (int i = 0; i < 64; i++) a += p[i] * fc1w[i * 32 + j];
        z[j] = fmaxf(a, 0.f);
    }
    float l[16]; float mx = -1e30f;
    #pragma unroll
    for (int k = 0; k < 16; k++) {
        float a = fc2b[k];
        #pragma unroll
        for (int j = 0; j < 32; j++) a += z[j] * fc2w[j * 16 + k];
        l[k] = a; mx = fmaxf(mx, a);
    }
    float s = 0.f;
    #pragma unroll
    for (int k = 0; k < 16; k++) { l[k] = expf(l[k] - mx); s += l[k]; }
    float invs = 1.0f / s;
    #pragma unroll
    for (int k = 0; k < 16; k++) out[g * 16 + k] = l[k] * invs;
}

extern "C" void kernel_launch(void* const* d_in, const int* in_sizes, int n_in,
                              void* d_out, int out_size) {
    const float* x     = (const float*)d_in[0];
    const int*   eidx  = (const int*)d_in[1];
    const int*   batch = (const int*)d_in[2];
    const float* W1 = (const float*)d_in[3];
    const float* b1 = (const float*)d_in[4];
    const float* W2 = (const float*)d_in[5];
    const float* b2 = (const float*)d_in[6];
    const float* W3 = (const float*)d_in[7];
    const float* b3 = (const float*)d_in[8];
    const float* fc1w = (const float*)d_in[9];
    const float* fc1b = (const float*)d_in[10];
    const float* fc2w = (const float*)d_in[11];
    const float* fc2b = (const float*)d_in[12];
    float* out = (float*)d_out;

    int N = in_sizes[0] / 128;
    int E = in_sizes[1] / 2;
    const int* src = eidx;
    const int* dst = eidx + E;

    // fork-join resources (created per call; kernel_launch is only invoked a
    // few times by the harness, replays re-execute the captured graph only)
    cudaStream_t s2;
    cudaStreamCreateWithFlags(&s2, cudaStreamNonBlocking);
    cudaEvent_t evDeg, evG1;
    cudaEventCreateWithFlags(&evDeg, cudaEventDisableTiming);
    cudaEventCreateWithFlags(&evG1, cudaEventDisableTiming);

    // zero accumulators via memset nodes
    void *p_deg, *p_pool, *p_cnt;
    cudaGetSymbolAddress(&p_deg, g_degcnt);
    cudaGetSymbolAddress(&p_pool, g_pool);
    cudaGetSymbolAddress(&p_cnt, g_cnt);
    cudaMemsetAsync(p_deg, 0, (size_t)N * 4, 0);
    cudaMemsetAsync(p_pool, 0, (size_t)NGRAPH * DMAX * 4, 0);
    cudaMemsetAsync(p_cnt, 0, (size_t)NGRAPH * 4, 0);

    // degree (needed by both branches)
    deg_kernel<<<(E + 255) / 256, 256>>>(dst, E);
    cudaEventRecord(evDeg, 0);

    // branch A (fork stream): dis -> gemm1 (hp for layer 1)
    cudaStreamWaitEvent(s2, evDeg, 0);
    dis_kernel<<<(N + 255) / 256, 256, 0, s2>>>(N);
    gemm_kernel<128, 32, 16><<<(N + 15) / 16, 128, 0, s2>>>(x, 0, W1, N);
    cudaEventRecord(evG1, s2);

    // branch B (main stream): CSR build
    int nb = (N + 511) / 512;
    scan1_kernel<<<nb, 512>>>(N);
    scan2_kernel<<<1, 512>>>(nb);
    scan3_kernel<<<(N + 255) / 256, 256>>>(N);
    fill_csr_kernel<<<(E + 255) / 256, 256>>>(src, dst, E);

    // join, then the serial layer chain
    cudaStreamWaitEvent(0, evG1, 0);

    int gth_blocks = (N + 7) / 8;
    int gemm_blocks = (N + 15) / 16;

    gather_kernel<32><<<gth_blocks, 256>>>(b1, N);
    gemm_kernel<32, 48, 16><<<gemm_blocks, 192>>>(nullptr, 1, W2, N);
    gather_kernel<48><<<gth_blocks, 256>>>(b2, N);
    gemm_kernel<48, 64, 16><<<gemm_blocks, 256>>>(nullptr, 1, W3, N);
    gather_kernel<64><<<gth_blocks, 256>>>(b3, N);

    pool_kernel<<<(N + 63) / 64, 64>>>(batch, N);
    mlp_kernel<<<(NGRAPH + 255) / 256, 256>>>(fc1w, fc1b, fc2w, fc2b, out);
}